// round 12
// baseline (speedup 1.0000x reference)
#include <cuda_runtime.h>

// Problem shape (fixed by the dataset)
#define BB 8
#define SS 128
#define RR 192
#define CC 192
#define NX (CC / 4)   // 48 float4 segments per row

#define RTILES (RR / 4)                // 48
#define STILES (SS / 2)                // 64
#define NTILES (BB * STILES * RTILES)  // 24576
#define OCC 6
#define NBLOCKS (148 * OCC)            // 888 persistent CTAs

// SPACING = (2.0, 1.5, 1.5) along (S, R, C)
#define INV2DX 0.25f
#define INV2DY 0.33333333333333333f
#define INV2DZ 0.33333333333333333f
#define INVDX2 0.25f
#define INVDY2 0.44444444444444444f
#define INVDZ2 0.44444444444444444f

__device__ __forceinline__ int clamp_i(int v, int lo, int hi) {
    return min(max(v, lo), hi);
}

__device__ __forceinline__ void pf_l2(const float* p) {
    asm volatile("prefetch.global.L2 [%0];" :: "l"(p));
}

// Compute one output float4 for one plane (scalar math — R4 proven path).
__device__ __forceinline__ float4 plane_out(const float4 c,
                                            const float4 xm, const float4 xp,
                                            const float4 ym, const float4 yp,
                                            const float left, const float right,
                                            const float4 d,
                                            const bool lo, const bool hi)
{
    const float ca[4]  = {c.x,  c.y,  c.z,  c.w};
    const float xma[4] = {xm.x, xm.y, xm.z, xm.w};
    const float xpa[4] = {xp.x, xp.y, xp.z, xp.w};
    const float yma[4] = {ym.x, ym.y, ym.z, ym.w};
    const float ypa[4] = {yp.x, yp.y, yp.z, yp.w};
    const float zma[4] = {left, c.x,  c.y,  c.z};
    const float zpa[4] = {c.y,  c.z,  c.w,  right};
    const float da[4]  = {d.x,  d.y,  d.z,  d.w};

    float Fxy[4], Gxy[4], oa[4];
    #pragma unroll
    for (int j = 0; j < 4; ++j) {
        const float gx = (xpa[j] - xma[j]) * INV2DX;
        const float gy = (ypa[j] - yma[j]) * INV2DY;
        Fxy[j] = gx * gx + gy * gy;
        Gxy[j] = (xpa[j] - 2.0f * ca[j] + xma[j]) * INVDX2
               + (ypa[j] - 2.0f * ca[j] + yma[j]) * INVDY2;
        const float gz = (zpa[j] - zma[j]) * INV2DZ;
        const float Gz = (zpa[j] - 2.0f * ca[j] + zma[j]) * INVDZ2;
        oa[j] = -0.5f * (Fxy[j] + gz * gz) - da[j] * (Gxy[j] + Gz);
    }

    if (lo) {
        // k=1 (comp 1): zm tap is Q(0)=P[col 1]=c.y
        const float gz1 = (c.z - c.y) * INV2DZ;
        const float Gz1 = (c.z - c.y) * INVDZ2;
        oa[1] = -0.5f * (Fxy[1] + gz1 * gz1) - da[1] * (Gxy[1] + Gz1);
        // k=0 (comp 0): all column taps clamp to col 1
        oa[0] = -0.5f * Fxy[1] - da[0] * Gxy[1];
    }
    if (hi) {
        // k=190 (comp 2): zp tap is Q(191)=P[col 190]=c.z
        const float gz2 = (c.z - c.y) * INV2DZ;
        const float Gz2 = (c.y - c.z) * INVDZ2;
        oa[2] = -0.5f * (Fxy[2] + gz2 * gz2) - da[2] * (Gxy[2] + Gz2);
        // k=191 (comp 3): all column taps clamp to col 190
        oa[3] = -0.5f * Fxy[2] - da[3] * Gxy[2];
    }

    return make_float4(oa[0], oa[1], oa[2], oa[3]);
}

__global__ __launch_bounds__(192, OCC)
void flowp_kernel_pf(const float* __restrict__ P,
                     const float* __restrict__ D,
                     float* __restrict__ out)
{
    const int tx = threadIdx.x;          // 0..47 : float4 index along C
    const int ty = threadIdx.y;          // 0..3  : r within tile
    const int k0 = tx * 4;
    const bool lo = (tx == 0);
    const bool hi = (tx == NX - 1);

    // Column edge offsets (constant across tiles)
    const int kl = lo ? k0 : k0 - 1;
    const int kr = hi ? CC - 1 : k0 + 4;

    for (int T = blockIdx.x; T < NTILES; T += NBLOCKS) {
        // ---- L2 prefetch for the NEXT tile (no registers held, no stalls) ----
        {
            const int Tp = min(T + NBLOCKS, NTILES - 1);
            const int rb   = Tp % RTILES;
            const int rest = Tp / RTILES;
            const int st   = rest & (STILES - 1);
            const int b    = rest >> 6;
            const int r  = rb * 4 + ty;
            const int s0 = st * 2;
            const int i0 = clamp_i(s0 - 1, 1, SS - 2);
            const int i1 = clamp_i(s0,     1, SS - 2);
            const int i2 = clamp_i(s0 + 1, 1, SS - 2);
            const int i3 = clamp_i(s0 + 2, 1, SS - 2);
            const int cr = clamp_i(r,     1, RR - 2);
            const int rm = clamp_i(r - 1, 1, RR - 2);
            const int rp = clamp_i(r + 1, 1, RR - 2);
            const int base = b * (SS * RR * CC);
            const float* Pb = P + base;
            pf_l2(Pb + (i0 * RR + cr) * CC + k0);
            pf_l2(Pb + (i1 * RR + cr) * CC + k0);
            pf_l2(Pb + (i2 * RR + cr) * CC + k0);
            pf_l2(Pb + (i3 * RR + cr) * CC + k0);
            pf_l2(Pb + (i1 * RR + rm) * CC + k0);
            pf_l2(Pb + (i1 * RR + rp) * CC + k0);
            pf_l2(Pb + (i2 * RR + rm) * CC + k0);
            pf_l2(Pb + (i2 * RR + rp) * CC + k0);
            const int pidx = base + (s0 * RR + r) * CC + k0;
            pf_l2(D + pidx);
            pf_l2(D + pidx + RR * CC);
        }

        // ---- current tile (same as R4) ----
        const int rb   = T % RTILES;
        const int rest = T / RTILES;
        const int st   = rest & (STILES - 1);
        const int b    = rest >> 6;          // / STILES (=64)

        const int r  = rb * 4 + ty;
        const int s0 = st * 2;

        const int i0 = clamp_i(s0 - 1, 1, SS - 2);
        const int i1 = clamp_i(s0,     1, SS - 2);
        const int i2 = clamp_i(s0 + 1, 1, SS - 2);
        const int i3 = clamp_i(s0 + 2, 1, SS - 2);

        const int cr = clamp_i(r,     1, RR - 2);
        const int rm = clamp_i(r - 1, 1, RR - 2);
        const int rp = clamp_i(r + 1, 1, RR - 2);

        // 32-bit indexing: total tensor is 37.75M elements < 2^31
        const int base = b * (SS * RR * CC);
        const float* Pb = P + base;

        const int rowA   = (i0 * RR + cr) * CC;
        const int rowC1  = (i1 * RR + cr) * CC;
        const int rowC2  = (i2 * RR + cr) * CC;
        const int rowBp  = (i3 * RR + cr) * CC;
        const int rowY1m = (i1 * RR + rm) * CC;
        const int rowY1p = (i1 * RR + rp) * CC;
        const int rowY2m = (i2 * RR + rm) * CC;
        const int rowY2p = (i2 * RR + rp) * CC;

        const float4 A   = __ldg((const float4*)(Pb + rowA   + k0));
        const float4 C1  = __ldg((const float4*)(Pb + rowC1  + k0));
        const float4 C2  = __ldg((const float4*)(Pb + rowC2  + k0));
        const float4 Bp  = __ldg((const float4*)(Pb + rowBp  + k0));
        const float4 Y1m = __ldg((const float4*)(Pb + rowY1m + k0));
        const float4 Y1p = __ldg((const float4*)(Pb + rowY1p + k0));
        const float4 Y2m = __ldg((const float4*)(Pb + rowY2m + k0));
        const float4 Y2p = __ldg((const float4*)(Pb + rowY2p + k0));

        const float l1 = __ldg(Pb + rowC1 + kl);
        const float r1 = __ldg(Pb + rowC1 + kr);
        const float l2 = __ldg(Pb + rowC2 + kl);
        const float r2 = __ldg(Pb + rowC2 + kr);

        const int idx0 = base + (s0 * RR + r) * CC + k0;
        const int idx1 = idx0 + RR * CC;
        const float4 d0 = __ldg((const float4*)(D + idx0));
        const float4 d1 = __ldg((const float4*)(D + idx1));

        const float4 o0 = plane_out(C1, A,  C2, Y1m, Y1p, l1, r1, d0, lo, hi);
        const float4 o1 = plane_out(C2, C1, Bp, Y2m, Y2p, l2, r2, d1, lo, hi);

        *((float4*)(out + idx0)) = o0;
        *((float4*)(out + idx1)) = o1;
    }
}

extern "C" void kernel_launch(void* const* d_in, const int* in_sizes, int n_in,
                              void* d_out, int out_size)
{
    // inputs (metadata order): t (unused), batch_P, D
    const float* P = (const float*)d_in[1];
    const float* D = (const float*)d_in[2];
    float* out = (float*)d_out;

    dim3 grid(NBLOCKS);
    dim3 block(NX, 4);   // 192 threads
    flowp_kernel_pf<<<grid, block>>>(P, D, out);
}

// round 13
// speedup vs baseline: 1.1859x; 1.1859x over previous
#include <cuda_runtime.h>

// Problem shape (fixed by the dataset)
#define BB 8
#define SS 128
#define RR 192
#define CC 192
#define NX (CC / 4)   // 48 float4 segments per row

#define RTILES (RR / 4)                // 48
#define STILES (SS / 2)                // 64 s-tiles (2 planes each)
#define NCOLS (BB * RTILES)            // 384 (b, r-tile) columns
#define SCHUNK 16                      // consecutive s-tiles per CTA
#define NCHUNKS (STILES / SCHUNK)      // 4
#define NBLOCKS (NCOLS * NCHUNKS)      // 1536 CTAs, fixed work each

// SPACING = (2.0, 1.5, 1.5) along (S, R, C)
#define INV2DX 0.25f
#define INV2DY 0.33333333333333333f
#define INV2DZ 0.33333333333333333f
#define INVDX2 0.25f
#define INVDY2 0.44444444444444444f
#define INVDZ2 0.44444444444444444f

__device__ __forceinline__ int clamp_i(int v, int lo, int hi) {
    return min(max(v, lo), hi);
}

// Compute one output float4 for one plane (scalar math — R4 proven path).
__device__ __forceinline__ float4 plane_out(const float4 c,
                                            const float4 xm, const float4 xp,
                                            const float4 ym, const float4 yp,
                                            const float left, const float right,
                                            const float4 d,
                                            const bool lo, const bool hi)
{
    const float ca[4]  = {c.x,  c.y,  c.z,  c.w};
    const float xma[4] = {xm.x, xm.y, xm.z, xm.w};
    const float xpa[4] = {xp.x, xp.y, xp.z, xp.w};
    const float yma[4] = {ym.x, ym.y, ym.z, ym.w};
    const float ypa[4] = {yp.x, yp.y, yp.z, yp.w};
    const float zma[4] = {left, c.x,  c.y,  c.z};
    const float zpa[4] = {c.y,  c.z,  c.w,  right};
    const float da[4]  = {d.x,  d.y,  d.z,  d.w};

    float Fxy[4], Gxy[4], oa[4];
    #pragma unroll
    for (int j = 0; j < 4; ++j) {
        const float gx = (xpa[j] - xma[j]) * INV2DX;
        const float gy = (ypa[j] - yma[j]) * INV2DY;
        Fxy[j] = gx * gx + gy * gy;
        Gxy[j] = (xpa[j] - 2.0f * ca[j] + xma[j]) * INVDX2
               + (ypa[j] - 2.0f * ca[j] + yma[j]) * INVDY2;
        const float gz = (zpa[j] - zma[j]) * INV2DZ;
        const float Gz = (zpa[j] - 2.0f * ca[j] + zma[j]) * INVDZ2;
        oa[j] = -0.5f * (Fxy[j] + gz * gz) - da[j] * (Gxy[j] + Gz);
    }

    if (lo) {
        // k=1 (comp 1): zm tap is Q(0)=P[col 1]=c.y
        const float gz1 = (c.z - c.y) * INV2DZ;
        const float Gz1 = (c.z - c.y) * INVDZ2;
        oa[1] = -0.5f * (Fxy[1] + gz1 * gz1) - da[1] * (Gxy[1] + Gz1);
        // k=0 (comp 0): all column taps clamp to col 1
        oa[0] = -0.5f * Fxy[1] - da[0] * Gxy[1];
    }
    if (hi) {
        // k=190 (comp 2): zp tap is Q(191)=P[col 190]=c.z
        const float gz2 = (c.z - c.y) * INV2DZ;
        const float Gz2 = (c.y - c.z) * INVDZ2;
        oa[2] = -0.5f * (Fxy[2] + gz2 * gz2) - da[2] * (Gxy[2] + Gz2);
        // k=191 (comp 3): all column taps clamp to col 190
        oa[3] = -0.5f * Fxy[2] - da[3] * Gxy[2];
    }

    return make_float4(oa[0], oa[1], oa[2], oa[3]);
}

__global__ __launch_bounds__(192, 6)
void flowp_kernel_swalk(const float* __restrict__ P,
                        const float* __restrict__ D,
                        float* __restrict__ out)
{
    const int tx = threadIdx.x;          // 0..47 : float4 index along C
    const int ty = threadIdx.y;          // 0..3  : r within tile
    const int k0 = tx * 4;
    const bool lo = (tx == 0);
    const bool hi = (tx == NX - 1);

    // Column edge offsets (constant across tiles)
    const int kl = lo ? k0 : k0 - 1;
    const int kr = hi ? CC - 1 : k0 + 4;

    // (b, r-tile) column + s-chunk for this CTA; walk s consecutively so
    // successive iterations reuse planes (i0'=i2, i1'=i3 -> same addresses,
    // L1 hits) instead of jumping to a cold region each iteration.
    const int col   = blockIdx.x % NCOLS;
    const int chunk = blockIdx.x / NCOLS;
    const int rb    = col % RTILES;
    const int b     = col / RTILES;
    const int st0   = chunk * SCHUNK;

    const int r  = rb * 4 + ty;
    const int cr = clamp_i(r,     1, RR - 2);
    const int rm = clamp_i(r - 1, 1, RR - 2);
    const int rp = clamp_i(r + 1, 1, RR - 2);

    const long long base = (long long)b * (SS * RR * CC);
    const float* Pb = P + base;

    #pragma unroll 1
    for (int j = 0; j < SCHUNK; ++j) {
        const int s0 = (st0 + j) * 2;

        const int i0 = clamp_i(s0 - 1, 1, SS - 2);
        const int i1 = clamp_i(s0,     1, SS - 2);
        const int i2 = clamp_i(s0 + 1, 1, SS - 2);
        const int i3 = clamp_i(s0 + 2, 1, SS - 2);

        const int rowA   = (i0 * RR + cr) * CC;
        const int rowC1  = (i1 * RR + cr) * CC;
        const int rowC2  = (i2 * RR + cr) * CC;
        const int rowBp  = (i3 * RR + cr) * CC;
        const int rowY1m = (i1 * RR + rm) * CC;
        const int rowY1p = (i1 * RR + rp) * CC;
        const int rowY2m = (i2 * RR + rm) * CC;
        const int rowY2p = (i2 * RR + rp) * CC;

        const float4 A   = __ldg((const float4*)(Pb + rowA   + k0));
        const float4 C1  = __ldg((const float4*)(Pb + rowC1  + k0));
        const float4 C2  = __ldg((const float4*)(Pb + rowC2  + k0));
        const float4 Bp  = __ldg((const float4*)(Pb + rowBp  + k0));
        const float4 Y1m = __ldg((const float4*)(Pb + rowY1m + k0));
        const float4 Y1p = __ldg((const float4*)(Pb + rowY1p + k0));
        const float4 Y2m = __ldg((const float4*)(Pb + rowY2m + k0));
        const float4 Y2p = __ldg((const float4*)(Pb + rowY2p + k0));

        const float l1 = __ldg(Pb + rowC1 + kl);
        const float r1 = __ldg(Pb + rowC1 + kr);
        const float l2 = __ldg(Pb + rowC2 + kl);
        const float r2 = __ldg(Pb + rowC2 + kr);

        const long long idx0 = base + ((long long)(s0 * RR + r)) * CC + k0;
        const long long idx1 = idx0 + (long long)RR * CC;
        const float4 d0 = __ldg((const float4*)(D + idx0));
        const float4 d1 = __ldg((const float4*)(D + idx1));

        const float4 o0 = plane_out(C1, A,  C2, Y1m, Y1p, l1, r1, d0, lo, hi);
        const float4 o1 = plane_out(C2, C1, Bp, Y2m, Y2p, l2, r2, d1, lo, hi);

        *((float4*)(out + idx0)) = o0;
        *((float4*)(out + idx1)) = o1;
    }
}

extern "C" void kernel_launch(void* const* d_in, const int* in_sizes, int n_in,
                              void* d_out, int out_size)
{
    // inputs (metadata order): t (unused), batch_P, D
    const float* P = (const float*)d_in[1];
    const float* D = (const float*)d_in[2];
    float* out = (float*)d_out;

    dim3 grid(NBLOCKS);
    dim3 block(NX, 4);   // 192 threads
    flowp_kernel_swalk<<<grid, block>>>(P, D, out);
}